// round 2
// baseline (speedup 1.0000x reference)
#include <cuda_runtime.h>
#include <math.h>

// SpatialGRU: B=64, C=16, L=64, R=64, U=64, D=208
// Wavefront (anti-diagonal) schedule, 2 kernels per wavefront:
//   phaseA: Y = [hq|x] @ [wr_w|wz_w]^T + bias   (sigmoid applied to rr part)
//   phaseB: h_new = tanh([rr*hu|x] @ [U_w|wij_w]^T + b), gate-softmax combine
// s-projections folded into GEMM K-dim (weights are already [W_h | W_s], K=208).

#define AS_STRIDE 210   // 208 + pad (avoid bank conflicts on strided row reads)
#define WS_STRIDE 68    // 64 + pad (float4-aligned)
#define SMEM_BYTES ((64*AS_STRIDE + 208*WS_STRIDE) * 4)

// h grid with zero-padded top row / left col: index (l+1)*65 + (r+1)
__device__ float g_H[65 * 65 * 64 * 64];
// wavefront scratch: Y[l][b][448]  (pre-activation for z-part, sigmoid for rr-part)
__device__ float g_Y[64 * 64 * 448];

__device__ __forceinline__ int hidx(int l, int r) { return (l + 1) * 65 + (r + 1); }

extern "C" __global__ void zero_boundary_kernel() {
    int tid = blockIdx.x * blockDim.x + threadIdx.x;
    const int total = 129 * 4096;
    for (int i = tid; i < total; i += gridDim.x * blockDim.x) {
        int cell = i >> 12;
        int off  = i & 4095;
        int idx = (cell < 65) ? cell : (cell - 64) * 65;  // l=-1 row, then r=-1 col
        g_H[(size_t)idx * 4096 + off] = 0.0f;
    }
}

extern __shared__ float smem[];

// ---------------- Phase A: stage-1 GEMM (M=64 rows per cell, K=208, N=448 in 7 tiles of 64)
extern "C" __global__ void __launch_bounds__(256, 1)
phaseA_kernel(const float* __restrict__ inputs,
              const float* __restrict__ wr_w, const float* __restrict__ wr_b,
              const float* __restrict__ wz_w, const float* __restrict__ wz_b,
              int d, int l0)
{
    float* As = smem;                    // [64][AS_STRIDE]  rows = b, cols = [h_top|h_left|h_diag|x]
    float* Ws = smem + 64 * AS_STRIDE;   // [208][WS_STRIDE] (transposed weight tile)

    const int kt  = blockIdx.x;          // N tile 0..6 (0-2 = rr/sigmoid, 3-6 = z/raw)
    const int l   = l0 + blockIdx.y;
    const int r   = d - l;
    const int tid = threadIdx.x;

    const float* Htop  = g_H + (size_t)hidx(l - 1, r)     * 4096;
    const float* Hleft = g_H + (size_t)hidx(l,     r - 1) * 4096;
    const float* Hdiag = g_H + (size_t)hidx(l - 1, r - 1) * 4096;

    // load hq sections (coalesced float4 from H)
    for (int i = tid; i < 1024; i += 256) {
        int b = i >> 4, u = (i & 15) << 2;
        float4 v = ((const float4*)Htop)[i];
        float* dst = &As[b * AS_STRIDE + u];
        dst[0] = v.x; dst[1] = v.y; dst[2] = v.z; dst[3] = v.w;
    }
    for (int i = tid; i < 1024; i += 256) {
        int b = i >> 4, u = (i & 15) << 2;
        float4 v = ((const float4*)Hleft)[i];
        float* dst = &As[b * AS_STRIDE + 64 + u];
        dst[0] = v.x; dst[1] = v.y; dst[2] = v.z; dst[3] = v.w;
    }
    for (int i = tid; i < 1024; i += 256) {
        int b = i >> 4, u = (i & 15) << 2;
        float4 v = ((const float4*)Hdiag)[i];
        float* dst = &As[b * AS_STRIDE + 128 + u];
        dst[0] = v.x; dst[1] = v.y; dst[2] = v.z; dst[3] = v.w;
    }
    // x section: inputs[b][c][l][r]
    for (int i = tid; i < 1024; i += 256) {
        int b = i >> 4, c = i & 15;
        As[b * AS_STRIDE + 192 + c] = inputs[((b * 16 + c) * 64 + l) * 64 + r];
    }
    // weight tile, transposed into smem: Ws[j][kk] = W[kt*64+kk][j]
    const float* wsrc = (kt < 3) ? (wr_w + (size_t)kt * 64 * 208)
                                 : (wz_w + (size_t)(kt - 3) * 64 * 208);
    for (int i = tid; i < 64 * 208; i += 256) {
        int kk = i / 208, j = i - kk * 208;
        Ws[j * WS_STRIDE + kk] = wsrc[i];
    }
    __syncthreads();

    const int tx = tid & 15, ty = tid >> 4;
    const int row0 = ty * 4, c0 = tx * 4;

    float acc[4][4];
#pragma unroll
    for (int i = 0; i < 4; i++)
#pragma unroll
        for (int j = 0; j < 4; j++) acc[i][j] = 0.0f;

    const float* A0 = &As[row0 * AS_STRIDE];
#pragma unroll 8
    for (int j = 0; j < 208; j++) {
        float a0 = A0[j];
        float a1 = A0[AS_STRIDE + j];
        float a2 = A0[2 * AS_STRIDE + j];
        float a3 = A0[3 * AS_STRIDE + j];
        float4 bv = *(const float4*)&Ws[j * WS_STRIDE + c0];
        acc[0][0] += a0 * bv.x; acc[0][1] += a0 * bv.y; acc[0][2] += a0 * bv.z; acc[0][3] += a0 * bv.w;
        acc[1][0] += a1 * bv.x; acc[1][1] += a1 * bv.y; acc[1][2] += a1 * bv.z; acc[1][3] += a1 * bv.w;
        acc[2][0] += a2 * bv.x; acc[2][1] += a2 * bv.y; acc[2][2] += a2 * bv.z; acc[2][3] += a2 * bv.w;
        acc[3][0] += a3 * bv.x; acc[3][1] += a3 * bv.y; acc[3][2] += a3 * bv.z; acc[3][3] += a3 * bv.w;
    }

    const int kbase = kt * 64 + c0;
    float bias[4];
#pragma unroll
    for (int cj = 0; cj < 4; cj++)
        bias[cj] = (kt < 3) ? wr_b[kbase + cj] : wz_b[kbase + cj - 192];

    float* Yl = g_Y + (size_t)l * 64 * 448;
#pragma unroll
    for (int ri = 0; ri < 4; ri++) {
#pragma unroll
        for (int cj = 0; cj < 4; cj++) {
            float y = acc[ri][cj] + bias[cj];
            if (kt < 3) y = 1.0f / (1.0f + __expf(-y));   // rr = sigmoid
            Yl[(size_t)(row0 + ri) * 448 + kbase + cj] = y;
        }
    }
}

// ---------------- Phase B: stage-2 GEMM (K=208, N=64) + softmax gates + state update
extern "C" __global__ void __launch_bounds__(256, 1)
phaseB_kernel(const float* __restrict__ inputs,
              const float* __restrict__ U_w,
              const float* __restrict__ wij_w, const float* __restrict__ wij_b,
              float* __restrict__ out,
              int d, int l0)
{
    float* As = smem;                    // [64][AS_STRIDE]  rows = b, cols = [rr*hu | x]
    float* Ws = smem + 64 * AS_STRIDE;   // [208][WS_STRIDE]

    const int l   = l0 + blockIdx.x;
    const int r   = d - l;
    const int tid = threadIdx.x;

    const float* Htop  = g_H + (size_t)hidx(l - 1, r)     * 4096;
    const float* Hleft = g_H + (size_t)hidx(l,     r - 1) * 4096;
    const float* Hdiag = g_H + (size_t)hidx(l - 1, r - 1) * 4096;
    const float* Yl    = g_Y + (size_t)l * 64 * 448;

    // A2[b][j] = rr[b][j] * hu[b][j],  hu = [h_left, h_top, h_diag]
    for (int i = tid; i < 4096; i += 256) {
        int b = i >> 6, u = i & 63;
        As[b * AS_STRIDE + u] = Yl[(size_t)b * 448 + u] * Hleft[i];
    }
    for (int i = tid; i < 4096; i += 256) {
        int b = i >> 6, u = i & 63;
        As[b * AS_STRIDE + 64 + u] = Yl[(size_t)b * 448 + 64 + u] * Htop[i];
    }
    for (int i = tid; i < 4096; i += 256) {
        int b = i >> 6, u = i & 63;
        As[b * AS_STRIDE + 128 + u] = Yl[(size_t)b * 448 + 128 + u] * Hdiag[i];
    }
    for (int i = tid; i < 1024; i += 256) {
        int b = i >> 4, c = i & 15;
        As[b * AS_STRIDE + 192 + c] = inputs[((b * 16 + c) * 64 + l) * 64 + r];
    }
    // W2[j][u]: U_w part (coalesced read over j), then wij part
    for (int i = tid; i < 64 * 192; i += 256) {
        int u = i / 192, jj = i - u * 192;
        Ws[jj * WS_STRIDE + u] = U_w[i];
    }
    for (int i = tid; i < 64 * 16; i += 256) {
        int u = i >> 4, c = i & 15;
        Ws[(192 + c) * WS_STRIDE + u] = wij_w[i];
    }
    __syncthreads();

    const int tx = tid & 15, ty = tid >> 4;
    const int row0 = ty * 4, c0 = tx * 4;

    float acc[4][4];
#pragma unroll
    for (int i = 0; i < 4; i++)
#pragma unroll
        for (int j = 0; j < 4; j++) acc[i][j] = 0.0f;

    const float* A0 = &As[row0 * AS_STRIDE];
#pragma unroll 8
    for (int j = 0; j < 208; j++) {
        float a0 = A0[j];
        float a1 = A0[AS_STRIDE + j];
        float a2 = A0[2 * AS_STRIDE + j];
        float a3 = A0[3 * AS_STRIDE + j];
        float4 bv = *(const float4*)&Ws[j * WS_STRIDE + c0];
        acc[0][0] += a0 * bv.x; acc[0][1] += a0 * bv.y; acc[0][2] += a0 * bv.z; acc[0][3] += a0 * bv.w;
        acc[1][0] += a1 * bv.x; acc[1][1] += a1 * bv.y; acc[1][2] += a1 * bv.z; acc[1][3] += a1 * bv.w;
        acc[2][0] += a2 * bv.x; acc[2][1] += a2 * bv.y; acc[2][2] += a2 * bv.z; acc[2][3] += a2 * bv.w;
        acc[3][0] += a3 * bv.x; acc[3][1] += a3 * bv.y; acc[3][2] += a3 * bv.z; acc[3][3] += a3 * bv.w;
    }

    float* Hcur = g_H + (size_t)hidx(l, r) * 4096;
    const bool is_last = (l == 63) && (r == 63);

#pragma unroll
    for (int ri = 0; ri < 4; ri++) {
        int b = row0 + ri;
        const float* zrow = Yl + (size_t)b * 448 + 192;
#pragma unroll
        for (int cj = 0; cj < 4; cj++) {
            int u = c0 + cj;
            float hnew = tanhf(acc[ri][cj] + wij_b[u]);
            float z0 = zrow[u];         // i (new)
            float z1 = zrow[64 + u];    // l (left)
            float z2 = zrow[128 + u];   // t (top)
            float z3 = zrow[192 + u];   // d (diag)
            float m = fmaxf(fmaxf(z0, z1), fmaxf(z2, z3));
            float e0 = __expf(z0 - m), e1 = __expf(z1 - m);
            float e2 = __expf(z2 - m), e3 = __expf(z3 - m);
            float inv = 1.0f / (e0 + e1 + e2 + e3);
            int bu = b * 64 + u;
            float h = (e1 * Hleft[bu] + e2 * Htop[bu] + e3 * Hdiag[bu] + e0 * hnew) * inv;
            Hcur[bu] = h;
            if (is_last) out[bu] = h;
        }
    }
}

extern "C" void kernel_launch(void* const* d_in, const int* in_sizes, int n_in,
                              void* d_out, int out_size)
{
    const float* inputs = (const float*)d_in[0];
    const float* wr_w   = (const float*)d_in[1];
    const float* wr_b   = (const float*)d_in[2];
    const float* wz_w   = (const float*)d_in[3];
    const float* wz_b   = (const float*)d_in[4];
    const float* wij_w  = (const float*)d_in[5];
    const float* wij_b  = (const float*)d_in[6];
    const float* U_w    = (const float*)d_in[7];
    float* out = (float*)d_out;

    cudaFuncSetAttribute(phaseA_kernel, cudaFuncAttributeMaxDynamicSharedMemorySize, SMEM_BYTES);
    cudaFuncSetAttribute(phaseB_kernel, cudaFuncAttributeMaxDynamicSharedMemorySize, SMEM_BYTES);

    zero_boundary_kernel<<<64, 256>>>();

    for (int d = 0; d < 127; d++) {
        int l0 = (d > 63) ? (d - 63) : 0;
        int l1 = (d < 63) ? d : 63;
        int nd = l1 - l0 + 1;
        phaseA_kernel<<<dim3(7, nd), 256, SMEM_BYTES>>>(inputs, wr_w, wr_b, wz_w, wz_b, d, l0);
        phaseB_kernel<<<nd, 256, SMEM_BYTES>>>(inputs, U_w, wij_w, wij_b, out, d, l0);
    }
}

// round 4
// speedup vs baseline: 1.1782x; 1.1782x over previous
#include <cuda_runtime.h>
#include <math.h>

// SpatialGRU B=64,C=16,L=R=64,U=64,K=208. Persistent row-pipelined kernel.
// CTA (p,q): rows {2p,2p+1}, batch quarter q (16 rows of B). 128 CTAs, 256 thr.
// Zigzag schedule: step s: even -> (2p, s/2), odd -> (2p+1, (s-1)/2).
// Cross-CTA dep only on row 2p-1 of CTA p-1 via L2 flags (acquire/release).

#define KDIM 208
#define A_STRIDE 20      // [208][20] floats, LDS.128-aligned (80B rows)
#define Y_STRIDE 449
#define W1_STRIDE 449    // float2 elements per k-row

// smem float offsets
#define WS2_OFF   0                    // 208*64 = 13312
#define B1_OFF    13312                // 448
#define WIJB_OFF  13760                // 64
#define A_OFF     13824                // 208*20 = 4160
#define Y_OFF     17984                // 16*449 = 7184
#define WS1_OFF   25168                // 2*16*449 float2 = 28736 floats
#define SMEM_FLOATS 53904
#define SMEM_BYTES (SMEM_FLOATS*4)

__device__ float g_H[65 * 65 * 64 * 64];   // padded H grid [hid][b][u]
__device__ float g_X[64 * 64 * 64 * 16];   // [l][r][b][c]
__device__ int   g_flag[4 * 64 * 64];      // [q][row][r]

__device__ __forceinline__ int hid(int l, int r) { return (l + 1) * 65 + (r + 1); }

#define FMA2(acc, a, b) asm("fma.rn.f32x2 %0, %1, %2, %0;" : "+l"(acc) : "l"(a), "l"(b))

extern "C" __global__ void init_kernel(const float* __restrict__ inputs) {
    int t = blockIdx.x * blockDim.x + threadIdx.x;
    int stride = gridDim.x * blockDim.x;
    for (int i = t; i < 129 * 4096; i += stride) {
        int cell = i >> 12, off = i & 4095;
        int idx = (cell < 65) ? cell : (cell - 64) * 65;
        g_H[(size_t)idx * 4096 + off] = 0.0f;
    }
    for (int i = t; i < 4 * 64 * 64; i += stride) g_flag[i] = 0;
    for (int i = t; i < 64 * 64 * 64 * 16; i += stride) {
        int r = i & 63, l = (i >> 6) & 63, c = (i >> 12) & 15, b = i >> 16;
        g_X[((((l << 6) + r) << 6) + b) * 16 + c] = inputs[i];
    }
}

extern __shared__ float smem[];

extern "C" __global__ void __launch_bounds__(256, 1)
pipeline_kernel(const float* __restrict__ wr_w, const float* __restrict__ wr_b,
                const float* __restrict__ wz_w, const float* __restrict__ wz_b,
                const float* __restrict__ wij_w, const float* __restrict__ wij_b,
                const float* __restrict__ U_w, float* __restrict__ out)
{
    const int tid = threadIdx.x;
    const int p = blockIdx.x >> 2;     // row pair 0..31
    const int q = blockIdx.x & 3;      // batch quarter
    const int b0 = q * 16;
    const int tx = tid & 63;           // n-lane
    const int ty = tid >> 6;           // m-block (4 rows)

    float* ws2   = smem + WS2_OFF;
    float* bias1 = smem + B1_OFF;
    float* wijb  = smem + WIJB_OFF;
    float* As    = smem + A_OFF;
    float* Ys    = smem + Y_OFF;
    float2* ws1  = (float2*)(smem + WS1_OFF);

    // ---- one-time preload: stage-2 weights, biases ----
    for (int i = tid; i < 208 * 64; i += 256) {
        int k = i >> 6, n = i & 63;
        ws2[i] = (k < 192) ? U_w[n * 192 + k] : wij_w[n * 16 + (k - 192)];
    }
    for (int i = tid; i < 448; i += 256) bias1[i] = (i < 192) ? wr_b[i] : wz_b[i - 192];
    if (tid < 64) wijb[tid] = wij_b[tid];
    __syncthreads();

    for (int s = 0; s < 128; s++) {
        const int sub = s & 1;
        const int r = s >> 1;
        const int l = 2 * p + sub;

        // ---- wait for row above (other CTA) ----
        if (sub == 0 && p > 0) {
            if (tid == 0) {
                const int* fp = &g_flag[(q * 64 + (2 * p - 1)) * 64 + r];
                int v;
                do {
                    asm volatile("ld.acquire.gpu.global.b32 %0, [%1];" : "=r"(v) : "l"(fp));
                    if (!v) __nanosleep(64);
                } while (!v);
            }
            __syncthreads();
        }

        const float* Htop  = g_H + (size_t)hid(l - 1, r) * 4096 + b0 * 64;
        const float* Hleft = g_H + (size_t)hid(l, r - 1) * 4096 + b0 * 64;
        const float* Hdiag = g_H + (size_t)hid(l - 1, r - 1) * 4096 + b0 * 64;
        const float* Xc    = g_X + ((size_t)((l << 6) + r) * 64 + b0) * 16;

        // ---- build A1[k][m] = [h_top | h_left | h_diag | x] ----
        for (int i = tid; i < 16 * KDIM; i += 256) {
            int m = i / KDIM, k = i - m * KDIM;
            float v;
            if (k < 64)        v = Htop[m * 64 + k];
            else if (k < 128)  v = Hleft[m * 64 + (k - 64)];
            else if (k < 192)  v = Hdiag[m * 64 + (k - 128)];
            else               v = Xc[m * 16 + (k - 192)];
            As[k * A_STRIDE + m] = v;
        }

        // ---- stage-1 GEMM: Y[16,448], W1 streamed in 13 chunks of 16 k ----
        float4 pf[7];
        {
#pragma unroll
            for (int i = 0; i < 7; i++) {
                int lin = tid + 256 * i;
                int n = lin >> 2, c4 = lin & 3;
                const float* row = (n < 192) ? (wr_w + (size_t)n * KDIM)
                                             : (wz_w + (size_t)(n - 192) * KDIM);
                pf[i] = *(const float4*)(row + c4 * 4);
            }
            float2* dst = ws1;
#pragma unroll
            for (int i = 0; i < 7; i++) {
                int lin = tid + 256 * i;
                int n = lin >> 2, c4 = lin & 3;
                dst[(4 * c4 + 0) * W1_STRIDE + n] = make_float2(pf[i].x, pf[i].x);
                dst[(4 * c4 + 1) * W1_STRIDE + n] = make_float2(pf[i].y, pf[i].y);
                dst[(4 * c4 + 2) * W1_STRIDE + n] = make_float2(pf[i].z, pf[i].z);
                dst[(4 * c4 + 3) * W1_STRIDE + n] = make_float2(pf[i].w, pf[i].w);
            }
        }
        __syncthreads();

        unsigned long long acc[2][7];
#pragma unroll
        for (int i = 0; i < 2; i++)
#pragma unroll
            for (int j = 0; j < 7; j++) acc[i][j] = 0ULL;

        for (int c = 0; c < 13; c++) {
            if (c < 12) {
#pragma unroll
                for (int i = 0; i < 7; i++) {
                    int lin = tid + 256 * i;
                    int n = lin >> 2, c4 = lin & 3;
                    const float* row = (n < 192) ? (wr_w + (size_t)n * KDIM)
                                                 : (wz_w + (size_t)(n - 192) * KDIM);
                    pf[i] = *(const float4*)(row + (c + 1) * 16 + c4 * 4);
                }
            }
            const unsigned long long* wb =
                (const unsigned long long*)(ws1 + (c & 1) * (16 * W1_STRIDE));
            const float* Abase = As + (c * 16) * A_STRIDE + 4 * ty;
#pragma unroll
            for (int kk = 0; kk < 16; kk++) {
                ulonglong2 av = *(const ulonglong2*)(Abase + kk * A_STRIDE);
#pragma unroll
                for (int j = 0; j < 7; j++) {
                    unsigned long long wd = wb[kk * W1_STRIDE + tx + 64 * j];
                    FMA2(acc[0][j], av.x, wd);
                    FMA2(acc[1][j], av.y, wd);
                }
            }
            __syncthreads();
            if (c < 12) {
                float2* dst = ws1 + ((c + 1) & 1) * (16 * W1_STRIDE);
#pragma unroll
                for (int i = 0; i < 7; i++) {
                    int lin = tid + 256 * i;
                    int n = lin >> 2, c4 = lin & 3;
                    dst[(4 * c4 + 0) * W1_STRIDE + n] = make_float2(pf[i].x, pf[i].x);
                    dst[(4 * c4 + 1) * W1_STRIDE + n] = make_float2(pf[i].y, pf[i].y);
                    dst[(4 * c4 + 2) * W1_STRIDE + n] = make_float2(pf[i].z, pf[i].z);
                    dst[(4 * c4 + 3) * W1_STRIDE + n] = make_float2(pf[i].w, pf[i].w);
                }
                __syncthreads();
            }
        }

        // ---- stage-1 epilogue: bias, sigmoid on rr (n<192), store Y ----
#pragma unroll
        for (int j = 0; j < 7; j++) {
            int n = tx + 64 * j;
            float bj = bias1[n];
#pragma unroll
            for (int i2 = 0; i2 < 2; i2++) {
                unsigned int lo, hi;
                asm("mov.b64 {%0,%1}, %2;" : "=r"(lo), "=r"(hi) : "l"(acc[i2][j]));
                float y0 = __uint_as_float(lo) + bj;
                float y1 = __uint_as_float(hi) + bj;
                if (j < 3) {
                    y0 = __fdividef(1.0f, 1.0f + __expf(-y0));
                    y1 = __fdividef(1.0f, 1.0f + __expf(-y1));
                }
                Ys[(4 * ty + 2 * i2 + 0) * Y_STRIDE + n] = y0;
                Ys[(4 * ty + 2 * i2 + 1) * Y_STRIDE + n] = y1;
            }
        }
        __syncthreads();

        // ---- build A2[k][m] = rr * [h_left | h_top | h_diag] ; x ----
        for (int i = tid; i < 16 * KDIM; i += 256) {
            int m = i / KDIM, k = i - m * KDIM;
            float v;
            if (k < 64)        v = Ys[m * Y_STRIDE + k] * Hleft[m * 64 + k];
            else if (k < 128)  v = Ys[m * Y_STRIDE + k] * Htop[m * 64 + (k - 64)];
            else if (k < 192)  v = Ys[m * Y_STRIDE + k] * Hdiag[m * 64 + (k - 128)];
            else               v = Xc[m * 16 + (k - 192)];
            As[k * A_STRIDE + m] = v;
        }
        __syncthreads();

        // ---- stage-2 GEMM: 16x64, K=208 ----
        unsigned long long acc2[2] = {0ULL, 0ULL};
        {
            const float* Abase = As + 4 * ty;
#pragma unroll 8
            for (int k = 0; k < KDIM; k++) {
                ulonglong2 av = *(const ulonglong2*)(Abase + k * A_STRIDE);
                float w = ws2[k * 64 + tx];
                unsigned int wi = __float_as_uint(w);
                unsigned long long wd;
                asm("mov.b64 %0, {%1,%2};" : "=l"(wd) : "r"(wi), "r"(wi));
                FMA2(acc2[0], av.x, wd);
                FMA2(acc2[1], av.y, wd);
            }
        }

        // ---- stage-2 epilogue: tanh, softmax gates, H update ----
        {
            float* Hout = g_H + (size_t)hid(l, r) * 4096 + b0 * 64;
            float wb = wijb[tx];
            const bool last = (l == 63) && (r == 63);
#pragma unroll
            for (int i2 = 0; i2 < 2; i2++) {
                unsigned int lo, hi;
                asm("mov.b64 {%0,%1}, %2;" : "=r"(lo), "=r"(hi) : "l"(acc2[i2]));
                float av[2] = {__uint_as_float(lo), __uint_as_float(hi)};
#pragma unroll
                for (int h2 = 0; h2 < 2; h2++) {
                    int m = 4 * ty + 2 * i2 + h2;
                    float hnew = tanhf(av[h2] + wb);
                    const float* zrow = Ys + m * Y_STRIDE + 192;
                    float z0 = zrow[tx], z1 = zrow[64 + tx];
                    float z2 = zrow[128 + tx], z3 = zrow[192 + tx];
                    float mx = fmaxf(fmaxf(z0, z1), fmaxf(z2, z3));
                    float e0 = __expf(z0 - mx), e1 = __expf(z1 - mx);
                    float e2 = __expf(z2 - mx), e3 = __expf(z3 - mx);
                    float inv = __fdividef(1.0f, e0 + e1 + e2 + e3);
                    float h = (e1 * Hleft[m * 64 + tx] + e2 * Htop[m * 64 + tx] +
                               e3 * Hdiag[m * 64 + tx] + e0 * hnew) * inv;
                    Hout[m * 64 + tx] = h;
                    if (last) out[(b0 + m) * 64 + tx] = h;
                }
            }
        }
        __syncthreads();

        // ---- publish flag for odd rows (consumed by CTA p+1) ----
        if (sub == 1 && tid == 0) {
            int* fp = &g_flag[(q * 64 + l) * 64 + r];
            asm volatile("st.release.gpu.global.b32 [%0], %1;" :: "l"(fp), "r"(1) : "memory");
        }
    }
}

extern "C" void kernel_launch(void* const* d_in, const int* in_sizes, int n_in,
                              void* d_out, int out_size)
{
    const float* wr_w   = (const float*)d_in[1];
    const float* wr_b   = (const float*)d_in[2];
    const float* wz_w   = (const float*)d_in[3];
    const float* wz_b   = (const float*)d_in[4];
    const float* wij_w  = (const float*)d_in[5];
    const float* wij_b  = (const float*)d_in[6];
    const float* U_w    = (const float*)d_in[7];
    const float* inputs = (const float*)d_in[0];
    float* out = (float*)d_out;

    cudaFuncSetAttribute(pipeline_kernel, cudaFuncAttributeMaxDynamicSharedMemorySize, SMEM_BYTES);

    init_kernel<<<256, 256>>>(inputs);
    pipeline_kernel<<<128, 256, SMEM_BYTES>>>(wr_w, wr_b, wz_w, wz_b,
                                              wij_w, wij_b, U_w, out);
}

// round 5
// speedup vs baseline: 2.6296x; 2.2318x over previous
#include <cuda_runtime.h>
#include <math.h>

// SpatialGRU B=64,C=16,L=R=64,U=64,K=208. Persistent row-pipelined kernel.
// CTA (p,q): rows {2p,2p+1}, batch quarter q (16 of B). 128 CTAs, 256 thr.
// GEMMs: W streamed L2->regs (read once, coalesced via pre-transposed copies),
// A broadcast from smem (m-paired float2), K split 4-way across thread groups,
// partials reduced through smem. 6 barriers/cell.

#define KDIM 208

// smem float offsets
#define P_OFF    0          // [4][7][8][64] float2 = 28672 floats (S2 reuses)
#define AS_OFF   28672      // [208][8] float2 = 3328 floats
#define YS_OFF   32000      // [16][449] = 7184
#define B1_OFF   39184      // 448
#define WIJB_OFF 39632      // 64
#define SMEM_FLOATS 39696
#define SMEM_BYTES (SMEM_FLOATS*4)

__device__ float g_H[65 * 65 * 64 * 64];   // padded H grid [hid][b][u]
__device__ float g_X[64 * 64 * 64 * 16];   // [l][r][b][c]
__device__ float g_Wt1[208 * 448];         // [k][n]  n<192: wr, else wz
__device__ float g_Wt2[208 * 64];          // [k][n]  k<192: U_w, else wij
__device__ int   g_flag[4 * 64 * 64];      // [q][row][r]

__device__ __forceinline__ int hid(int l, int r) { return (l + 1) * 65 + (r + 1); }

#define FMA2(acc, a, b) asm("fma.rn.f32x2 %0, %1, %2, %0;" : "+l"(acc) : "l"(a), "l"(b))

__device__ __forceinline__ unsigned long long dup2(float w) {
    unsigned int wi = __float_as_uint(w);
    unsigned long long d;
    asm("mov.b64 %0, {%1,%2};" : "=l"(d) : "r"(wi), "r"(wi));
    return d;
}
__device__ __forceinline__ float2 unpack2(unsigned long long v) {
    unsigned int a, b;
    asm("mov.b64 {%0,%1}, %2;" : "=r"(a), "=r"(b) : "l"(v));
    return make_float2(__uint_as_float(a), __uint_as_float(b));
}

extern "C" __global__ void init_kernel(const float* __restrict__ inputs,
                                       const float* __restrict__ wr_w,
                                       const float* __restrict__ wz_w,
                                       const float* __restrict__ U_w,
                                       const float* __restrict__ wij_w)
{
    int t = blockIdx.x * blockDim.x + threadIdx.x;
    int stride = gridDim.x * blockDim.x;
    for (int i = t; i < 129 * 4096; i += stride) {
        int cell = i >> 12, off = i & 4095;
        int idx = (cell < 65) ? cell : (cell - 64) * 65;
        g_H[(size_t)idx * 4096 + off] = 0.0f;
    }
    for (int i = t; i < 4 * 64 * 64; i += stride) g_flag[i] = 0;
    for (int i = t; i < 64 * 64 * 64 * 16; i += stride) {
        int r = i & 63, l = (i >> 6) & 63, c = (i >> 12) & 15, b = i >> 16;
        g_X[((((l << 6) + r) << 6) + b) * 16 + c] = inputs[i];
    }
    for (int i = t; i < 208 * 448; i += stride) {
        int k = i / 448, n = i - k * 448;
        g_Wt1[i] = (n < 192) ? wr_w[n * KDIM + k] : wz_w[(n - 192) * KDIM + k];
    }
    for (int i = t; i < 208 * 64; i += stride) {
        int k = i >> 6, n = i & 63;
        g_Wt2[i] = (k < 192) ? U_w[n * 192 + k] : wij_w[n * 16 + (k - 192)];
    }
}

extern __shared__ float smem[];

#define LDW1(dst, KK) { const float* _b = wp + (size_t)(KK) * 448; \
    _Pragma("unroll") for (int _j = 0; _j < 7; _j++) dst[_j] = _b[_j * 64]; }
#define LDA(dst, KK) { const ulonglong2* _r = Ab + (KK) * 4; \
    dst[0] = _r[0]; dst[1] = _r[1]; dst[2] = _r[2]; dst[3] = _r[3]; }
#define FMAB(WD, A) { _Pragma("unroll") for (int _j = 0; _j < 7; _j++) { \
    FMA2(acc[_j][0], A[0].x, WD[_j]); FMA2(acc[_j][1], A[0].y, WD[_j]); \
    FMA2(acc[_j][2], A[1].x, WD[_j]); FMA2(acc[_j][3], A[1].y, WD[_j]); \
    FMA2(acc[_j][4], A[2].x, WD[_j]); FMA2(acc[_j][5], A[2].y, WD[_j]); \
    FMA2(acc[_j][6], A[3].x, WD[_j]); FMA2(acc[_j][7], A[3].y, WD[_j]); } }

extern "C" __global__ void __launch_bounds__(256, 1)
pipeline_kernel(const float* __restrict__ wr_b, const float* __restrict__ wz_b,
                const float* __restrict__ wij_b, float* __restrict__ out)
{
    const int tid = threadIdx.x;
    const int p = blockIdx.x >> 2;     // row pair 0..31
    const int q = blockIdx.x & 3;      // batch quarter
    const int b0 = q * 16;
    const int nl = tid & 63;           // n-lane
    const int kg = tid >> 6;           // k-group (52 k each)
    const int k0 = kg * 52;
    const int mp_b = tid >> 5;         // build-phase m-pair 0..7
    const int kb_b = tid & 31;

    float2* Pv   = (float2*)(smem + P_OFF);
    float2* As   = (float2*)(smem + AS_OFF);
    float*  Ys   = smem + YS_OFF;
    float*  bias1 = smem + B1_OFF;
    float*  wijb  = smem + WIJB_OFF;

    for (int i = tid; i < 448; i += 256) bias1[i] = (i < 192) ? wr_b[i] : wz_b[i - 192];
    if (tid < 64) wijb[tid] = wij_b[tid];
    __syncthreads();

    const float* wp  = g_Wt1 + (size_t)k0 * 448 + nl;
    const float* wp2 = g_Wt2 + (size_t)k0 * 64 + nl;
    const ulonglong2* Ab = (const ulonglong2*)As + (size_t)k0 * 4;

    for (int s = 0; s < 128; s++) {
        const int sub = s & 1;
        const int r = s >> 1;
        const int l = 2 * p + sub;

        if (sub == 0 && p > 0) {
            if (tid == 0) {
                const int* fp = &g_flag[(q * 64 + (2 * p - 1)) * 64 + r];
                int v;
                do {
                    asm volatile("ld.acquire.gpu.global.b32 %0, [%1];" : "=r"(v) : "l"(fp));
                    if (!v) __nanosleep(64);
                } while (!v);
            }
            __syncthreads();
        }

        const float* Htop  = g_H + (size_t)hid(l - 1, r) * 4096 + b0 * 64;
        const float* Hleft = g_H + (size_t)hid(l, r - 1) * 4096 + b0 * 64;
        const float* Hdiag = g_H + (size_t)hid(l - 1, r - 1) * 4096 + b0 * 64;
        const float* Xc    = g_X + ((size_t)((l << 6) + r) * 64 + b0) * 16;

        // ---- build A1[k][mp] = m-paired {h_top|h_left|h_diag|x} ----
        {
            const int m0 = 2 * mp_b, m1 = m0 + 1;
#pragma unroll
            for (int c = 0; c < 7; c++) {
                int k = kb_b + 32 * c;
                if (k < KDIM) {
                    float v0, v1;
                    if (k < 192) {
                        const float* Hs = (k < 64) ? Htop : ((k < 128) ? Hleft : Hdiag);
                        int ko = k & 63;
                        v0 = Hs[m0 * 64 + ko];
                        v1 = Hs[m1 * 64 + ko];
                    } else {
                        v0 = Xc[m0 * 16 + (k - 192)];
                        v1 = Xc[m1 * 16 + (k - 192)];
                    }
                    As[k * 8 + mp_b] = make_float2(v0, v1);
                }
            }
        }
        __syncthreads();

        // ---- stage-1 GEMM: acc[j][mp], W from L2 (pipelined), A broadcast ----
        unsigned long long acc[7][8];
#pragma unroll
        for (int j = 0; j < 7; j++)
#pragma unroll
            for (int m = 0; m < 8; m++) acc[j][m] = 0ULL;
        {
            float wA[7], wB[7];
            ulonglong2 aA[4], aB[4];
            LDW1(wA, 0); LDW1(wB, 1); LDA(aA, 0);
            for (int kk = 0; kk < 52; kk += 2) {
                unsigned long long wdA[7];
#pragma unroll
                for (int j = 0; j < 7; j++) wdA[j] = dup2(wA[j]);
                LDA(aB, kk + 1);
                if (kk + 2 < 52) LDW1(wA, kk + 2);
                FMAB(wdA, aA);
                unsigned long long wdB[7];
#pragma unroll
                for (int j = 0; j < 7; j++) wdB[j] = dup2(wB[j]);
                if (kk + 2 < 52) LDA(aA, kk + 2);
                if (kk + 3 < 52) LDW1(wB, kk + 3);
                FMAB(wdB, aB);
            }
        }
        // partial store: P[kg][j][mp][nl]
#pragma unroll
        for (int j = 0; j < 7; j++)
#pragma unroll
            for (int m = 0; m < 8; m++)
                Pv[(size_t)kg * 3584 + (j * 8 + m) * 64 + nl] = unpack2(acc[j][m]);
        __syncthreads();

        // ---- reduce partials + bias + sigmoid(rr) -> Ys[m][n] ----
#pragma unroll
        for (int i = 0; i < 14; i++) {
            int f = tid + 256 * i;
            int nl2 = f & 63, rest = f >> 6;
            int m = rest & 7, j = rest >> 3;
            int base = (j * 8 + m) * 64 + nl2;
            float2 s0 = Pv[base], s1 = Pv[3584 + base];
            float2 s2 = Pv[7168 + base], s3 = Pv[10752 + base];
            int n = nl2 + 64 * j;
            float b = bias1[n];
            float x0 = ((s0.x + s1.x) + (s2.x + s3.x)) + b;
            float x1 = ((s0.y + s1.y) + (s2.y + s3.y)) + b;
            if (j < 3) {
                x0 = __fdividef(1.0f, 1.0f + __expf(-x0));
                x1 = __fdividef(1.0f, 1.0f + __expf(-x1));
            }
            Ys[(2 * m) * 449 + n] = x0;
            Ys[(2 * m + 1) * 449 + n] = x1;
        }
        __syncthreads();

        // ---- build A2[k][mp] = m-paired {rr*[h_left|h_top|h_diag] | x} ----
        {
            const int m0 = 2 * mp_b, m1 = m0 + 1;
#pragma unroll
            for (int c = 0; c < 7; c++) {
                int k = kb_b + 32 * c;
                if (k < KDIM) {
                    float v0, v1;
                    if (k < 192) {
                        const float* Hs = (k < 64) ? Hleft : ((k < 128) ? Htop : Hdiag);
                        int ko = k & 63;
                        v0 = Ys[m0 * 449 + k] * Hs[m0 * 64 + ko];
                        v1 = Ys[m1 * 449 + k] * Hs[m1 * 64 + ko];
                    } else {
                        v0 = Xc[m0 * 16 + (k - 192)];
                        v1 = Xc[m1 * 16 + (k - 192)];
                    }
                    As[k * 8 + mp_b] = make_float2(v0, v1);
                }
            }
        }
        __syncthreads();

        // ---- stage-2 GEMM: acc2[mp], n = nl ----
        unsigned long long acc2[8];
#pragma unroll
        for (int m = 0; m < 8; m++) acc2[m] = 0ULL;
        {
            float w4[4];
#pragma unroll
            for (int i = 0; i < 4; i++) w4[i] = wp2[i * 64];
#pragma unroll 4
            for (int kk = 0; kk < 52; kk++) {
                ulonglong2 a[4];
                LDA(a, kk);
                unsigned long long wd = dup2(w4[kk & 3]);
                if (kk + 4 < 52) w4[kk & 3] = wp2[(kk + 4) * 64];
                FMA2(acc2[0], a[0].x, wd); FMA2(acc2[1], a[0].y, wd);
                FMA2(acc2[2], a[1].x, wd); FMA2(acc2[3], a[1].y, wd);
                FMA2(acc2[4], a[2].x, wd); FMA2(acc2[5], a[2].y, wd);
                FMA2(acc2[6], a[3].x, wd); FMA2(acc2[7], a[3].y, wd);
            }
        }
        // partial store: P2[kg][mp][nl]
#pragma unroll
        for (int m = 0; m < 8; m++)
            Pv[(size_t)kg * 512 + m * 64 + nl] = unpack2(acc2[m]);
        __syncthreads();

        // ---- reduce + tanh + softmax gates + H update ----
        {
            float* Hout = g_H + (size_t)hid(l, r) * 4096 + b0 * 64;
            const bool last = (l == 63) && (r == 63);
#pragma unroll
            for (int i = 0; i < 2; i++) {
                int f = tid + 256 * i;
                int nl2 = f & 63, m = f >> 6;
                int base = m * 64 + nl2;
                float2 s0 = Pv[base], s1 = Pv[512 + base];
                float2 s2 = Pv[1024 + base], s3 = Pv[1536 + base];
                float wb = wijb[nl2];
                float a0 = ((s0.x + s1.x) + (s2.x + s3.x)) + wb;
                float a1 = ((s0.y + s1.y) + (s2.y + s3.y)) + wb;
                float av[2] = {a0, a1};
#pragma unroll
                for (int h2 = 0; h2 < 2; h2++) {
                    int mm = 2 * m + h2;
                    int u = nl2;
                    float hnew = tanhf(av[h2]);
                    const float* zrow = Ys + mm * 449 + 192;
                    float z0 = zrow[u], z1 = zrow[64 + u];
                    float z2 = zrow[128 + u], z3 = zrow[192 + u];
                    float mx = fmaxf(fmaxf(z0, z1), fmaxf(z2, z3));
                    float e0 = __expf(z0 - mx), e1 = __expf(z1 - mx);
                    float e2 = __expf(z2 - mx), e3 = __expf(z3 - mx);
                    float inv = __fdividef(1.0f, e0 + e1 + e2 + e3);
                    float h = (e1 * Hleft[mm * 64 + u] + e2 * Htop[mm * 64 + u] +
                               e3 * Hdiag[mm * 64 + u] + e0 * hnew) * inv;
                    Hout[mm * 64 + u] = h;
                    if (last) out[(b0 + mm) * 64 + u] = h;
                }
            }
        }
        __syncthreads();

        if (sub == 1 && tid == 0) {
            __threadfence();
            int* fp = &g_flag[(q * 64 + l) * 64 + r];
            asm volatile("st.release.gpu.global.b32 [%0], %1;" :: "l"(fp), "r"(1) : "memory");
        }
    }
}

extern "C" void kernel_launch(void* const* d_in, const int* in_sizes, int n_in,
                              void* d_out, int out_size)
{
    const float* inputs = (const float*)d_in[0];
    const float* wr_w   = (const float*)d_in[1];
    const float* wr_b   = (const float*)d_in[2];
    const float* wz_w   = (const float*)d_in[3];
    const float* wz_b   = (const float*)d_in[4];
    const float* wij_w  = (const float*)d_in[5];
    const float* wij_b  = (const float*)d_in[6];
    const float* U_w    = (const float*)d_in[7];
    float* out = (float*)d_out;

    cudaFuncSetAttribute(pipeline_kernel, cudaFuncAttributeMaxDynamicSharedMemorySize, SMEM_BYTES);

    init_kernel<<<512, 256>>>(inputs, wr_w, wz_w, U_w, wij_w);
    pipeline_kernel<<<128, 256, SMEM_BYTES>>>(wr_b, wz_b, wij_b, out);
}

// round 6
// speedup vs baseline: 2.8406x; 1.0802x over previous
#include <cuda_runtime.h>
#include <math.h>

// SpatialGRU B=64,C=16,L=R=64,U=64,K=208. Persistent row-pipelined kernel.
// CTA (p,q): rows {2p,2p+1}, batch quarter q (16 of B). 128 CTAs, 256 thr.
// Round-6: softmax-differenced z weights (N1 448->384), smem H ring (one
// global H read per step-pair, only odd rows stored), hoisted W prologues.

#define KDIM 208
#define JT   6
#define N1   384
#define YSTR 385

// smem float offsets
#define P_OFF    0          // [4][6][8][64] float2 = 24576 floats
#define AS_OFF   24576      // [208][8] float2 = 3328
#define YS_OFF   27904      // [16][385] = 6160
#define HE_OFF   34064      // [2][16][64] = 2048   (own even row, dbl-buf)
#define HO_OFF   36112      // [2][16][64] = 2048   (own odd row)
#define HT_OFF   38160      // [2][16][64] = 2048   (fetched top row / diag)
#define B1_OFF   40208      // 384
#define WIJB_OFF 40592      // 64
#define SMEM_FLOATS 40656
#define SMEM_BYTES (SMEM_FLOATS*4)

__device__ float g_H[64 * 64 * 64 * 64];   // [l][r][b][u]; only odd l used
__device__ float g_X[64 * 64 * 64 * 16];   // [l][r][b][c]
__device__ float g_Wt1[208 * 384];         // [k][n] n<192: wr ; n>=192: wz diffs
__device__ float g_Wt2[208 * 64];          // [k][n] k<192: U_w ; else wij
__device__ int   g_flag[4 * 64 * 64];      // [q][row][r]

#define FMA2(acc, a, b) asm("fma.rn.f32x2 %0, %1, %2, %0;" : "+l"(acc) : "l"(a), "l"(b))

__device__ __forceinline__ unsigned long long dup2(float w) {
    unsigned int wi = __float_as_uint(w);
    unsigned long long d;
    asm("mov.b64 %0, {%1,%2};" : "=l"(d) : "r"(wi), "r"(wi));
    return d;
}
__device__ __forceinline__ float2 unpack2(unsigned long long v) {
    unsigned int a, b;
    asm("mov.b64 {%0,%1}, %2;" : "=r"(a), "=r"(b) : "l"(v));
    return make_float2(__uint_as_float(a), __uint_as_float(b));
}
__device__ __forceinline__ float fast_tanh(float x) {
    x = fminf(fmaxf(x, -15.0f), 15.0f);
    float e = __expf(2.0f * x);
    return __fdividef(e - 1.0f, e + 1.0f);
}

extern "C" __global__ void init_kernel(const float* __restrict__ inputs,
                                       const float* __restrict__ wr_w,
                                       const float* __restrict__ wz_w,
                                       const float* __restrict__ U_w,
                                       const float* __restrict__ wij_w)
{
    int t = blockIdx.x * blockDim.x + threadIdx.x;
    int stride = gridDim.x * blockDim.x;
    for (int i = t; i < 4 * 64 * 64; i += stride) g_flag[i] = 0;
    for (int i = t; i < 64 * 64 * 64 * 16; i += stride) {
        int r = i & 63, l = (i >> 6) & 63, c = (i >> 12) & 15, b = i >> 16;
        g_X[((((l << 6) + r) << 6) + b) * 16 + c] = inputs[i];
    }
    for (int i = t; i < 208 * 384; i += stride) {
        int k = i / 384, n = i - k * 384;
        if (n < 192) {
            g_Wt1[i] = wr_w[n * KDIM + k];
        } else {
            int tt = n - 192, g = tt >> 6, u = tt & 63;
            g_Wt1[i] = wz_w[(64 * (g + 1) + u) * KDIM + k] - wz_w[u * KDIM + k];
        }
    }
    for (int i = t; i < 208 * 64; i += stride) {
        int k = i >> 6, n = i & 63;
        g_Wt2[i] = (k < 192) ? U_w[n * 192 + k] : wij_w[n * 16 + (k - 192)];
    }
}

extern __shared__ float smem[];

#define LDW1(dst, KK) { const float* _b = wp + (size_t)(KK) * N1; \
    _Pragma("unroll") for (int _j = 0; _j < JT; _j++) dst[_j] = _b[_j * 64]; }
#define LDA(dst, KK) { const ulonglong2* _r = Ab + (KK) * 4; \
    dst[0] = _r[0]; dst[1] = _r[1]; dst[2] = _r[2]; dst[3] = _r[3]; }
#define FMAB(WD, A) { _Pragma("unroll") for (int _j = 0; _j < JT; _j++) { \
    FMA2(acc[_j][0], A[0].x, WD[_j]); FMA2(acc[_j][1], A[0].y, WD[_j]); \
    FMA2(acc[_j][2], A[1].x, WD[_j]); FMA2(acc[_j][3], A[1].y, WD[_j]); \
    FMA2(acc[_j][4], A[2].x, WD[_j]); FMA2(acc[_j][5], A[2].y, WD[_j]); \
    FMA2(acc[_j][6], A[3].x, WD[_j]); FMA2(acc[_j][7], A[3].y, WD[_j]); } }

extern "C" __global__ void __launch_bounds__(256, 1)
pipeline_kernel(const float* __restrict__ wr_b, const float* __restrict__ wz_b,
                const float* __restrict__ wij_b, float* __restrict__ out)
{
    const int tid = threadIdx.x;
    const int p = blockIdx.x >> 2;     // row pair 0..31
    const int q = blockIdx.x & 3;      // batch quarter
    const int b0 = q * 16;
    const int nl = tid & 63;           // n-lane
    const int kg = tid >> 6;           // k-group (52 k each)
    const int k0 = kg * 52;
    const int mp_b = tid >> 5;         // build-phase m-pair 0..7
    const int kb_b = tid & 31;

    float2* Pv    = (float2*)(smem + P_OFF);
    float2* As    = (float2*)(smem + AS_OFF);
    float*  Ys    = smem + YS_OFF;
    float*  He    = smem + HE_OFF;
    float*  Ho    = smem + HO_OFF;
    float*  Ht    = smem + HT_OFF;
    float*  bias1 = smem + B1_OFF;
    float*  wijb  = smem + WIJB_OFF;

    for (int i = tid; i < 384; i += 256) {
        float b;
        if (i < 192) b = wr_b[i];
        else { int tt = i - 192, g = tt >> 6, u = tt & 63;
               b = wz_b[64 * (g + 1) + u] - wz_b[u]; }
        bias1[i] = b;
    }
    if (tid < 64) wijb[tid] = wij_b[tid];
    for (int i = tid; i < 6144; i += 256) He[i] = 0.0f;   // He,Ho,Ht contiguous
    __syncthreads();

    const float* wp  = g_Wt1 + (size_t)k0 * N1 + nl;
    const float* wp2 = g_Wt2 + (size_t)k0 * 64 + nl;
    const ulonglong2* Ab = (const ulonglong2*)As + (size_t)k0 * 4;

    for (int s = 0; s < 128; s++) {
        const int sub = s & 1;
        const int r = s >> 1;
        const int l = 2 * p + sub;
        const int rb = r & 1, rp = rb ^ 1;

        const float *hl_s, *ht_s, *hd_s;
        float* hdst;
        if (sub == 0) { hl_s = He + rp * 1024; ht_s = Ht + rb * 1024;
                        hd_s = Ht + rp * 1024; hdst = He + rb * 1024; }
        else          { hl_s = Ho + rp * 1024; ht_s = He + rb * 1024;
                        hd_s = He + rp * 1024; hdst = Ho + rb * 1024; }

        if (sub == 0 && p > 0) {
            if (tid == 0) {
                const int* fp = &g_flag[(q * 64 + (2 * p - 1)) * 64 + r];
                int v;
                do {
                    asm volatile("ld.acquire.gpu.global.b32 %0, [%1];" : "=r"(v) : "l"(fp));
                    if (!v) __nanosleep(64);
                } while (!v);
            }
            __syncthreads();
        }

        const float* Xc = g_X + ((size_t)((l << 6) + r) * 64 + b0) * 16;
        const float* Gtop = g_H + ((size_t)((2 * p - 1) * 64 + r)) * 4096 + b0 * 64;
        float* Htcur = Ht + rb * 1024;

        // ---- build A1[k][mp] = m-paired {h_top|h_left|h_diag|x} (smem sources) ----
        {
            const int m0 = 2 * mp_b, m1 = m0 + 1;
#pragma unroll
            for (int c = 0; c < 7; c++) {
                int k = kb_b + 32 * c;
                if (k < KDIM) {
                    float v0, v1;
                    if (k < 64) {
                        if (sub == 0) {
                            if (p > 0) {
                                v0 = Gtop[m0 * 64 + k]; v1 = Gtop[m1 * 64 + k];
                                Htcur[m0 * 64 + k] = v0; Htcur[m1 * 64 + k] = v1;
                            } else { v0 = 0.0f; v1 = 0.0f; }
                        } else {
                            v0 = ht_s[m0 * 64 + k]; v1 = ht_s[m1 * 64 + k];
                        }
                    } else if (k < 128) {
                        int ko = k - 64;
                        v0 = hl_s[m0 * 64 + ko]; v1 = hl_s[m1 * 64 + ko];
                    } else if (k < 192) {
                        int ko = k - 128;
                        v0 = hd_s[m0 * 64 + ko]; v1 = hd_s[m1 * 64 + ko];
                    } else {
                        v0 = Xc[m0 * 16 + (k - 192)]; v1 = Xc[m1 * 16 + (k - 192)];
                    }
                    As[k * 8 + mp_b] = make_float2(v0, v1);
                }
            }
        }
        // hoisted stage-1 W prologue (independent of As)
        float wA[JT], wB[JT];
        LDW1(wA, 0); LDW1(wB, 1);
        __syncthreads();

        // ---- stage-1 GEMM: acc[j][mp], W from L2, A broadcast from smem ----
        unsigned long long acc[JT][8];
#pragma unroll
        for (int j = 0; j < JT; j++)
#pragma unroll
            for (int m = 0; m < 8; m++) acc[j][m] = 0ULL;
        {
            ulonglong2 aA[4], aB[4];
            LDA(aA, 0);
            for (int kk = 0; kk < 52; kk += 2) {
                unsigned long long wdA[JT];
#pragma unroll
                for (int j = 0; j < JT; j++) wdA[j] = dup2(wA[j]);
                LDA(aB, kk + 1);
                if (kk + 2 < 52) LDW1(wA, kk + 2);
                FMAB(wdA, aA);
                unsigned long long wdB[JT];
#pragma unroll
                for (int j = 0; j < JT; j++) wdB[j] = dup2(wB[j]);
                if (kk + 2 < 52) LDA(aA, kk + 2);
                if (kk + 3 < 52) LDW1(wB, kk + 3);
                FMAB(wdB, aB);
            }
        }
#pragma unroll
        for (int j = 0; j < JT; j++)
#pragma unroll
            for (int m = 0; m < 8; m++)
                Pv[(size_t)kg * 3072 + (j * 8 + m) * 64 + nl] = unpack2(acc[j][m]);
        __syncthreads();

        // ---- reduce partials + bias; sigmoid on rr (j<3) -> Ys[m][n] ----
#pragma unroll
        for (int i = 0; i < 12; i++) {
            int f = tid + 256 * i;
            int nl2 = f & 63, rest = f >> 6;
            int m = rest & 7, j = rest >> 3;
            int base = (j * 8 + m) * 64 + nl2;
            float2 s0 = Pv[base], s1 = Pv[3072 + base];
            float2 s2 = Pv[6144 + base], s3 = Pv[9216 + base];
            int n = nl2 + 64 * j;
            float b = bias1[n];
            float x0 = ((s0.x + s1.x) + (s2.x + s3.x)) + b;
            float x1 = ((s0.y + s1.y) + (s2.y + s3.y)) + b;
            if (j < 3) {
                x0 = __fdividef(1.0f, 1.0f + __expf(-x0));
                x1 = __fdividef(1.0f, 1.0f + __expf(-x1));
            }
            Ys[(2 * m) * YSTR + n] = x0;
            Ys[(2 * m + 1) * YSTR + n] = x1;
        }
        // hoisted stage-2 W prologue
        float w4[4];
#pragma unroll
        for (int i = 0; i < 4; i++) w4[i] = wp2[i * 64];
        __syncthreads();

        // ---- build A2[k][mp] = m-paired {rr*[h_left|h_top|h_diag] | x} ----
        {
            const int m0 = 2 * mp_b, m1 = m0 + 1;
#pragma unroll
            for (int c = 0; c < 7; c++) {
                int k = kb_b + 32 * c;
                if (k < KDIM) {
                    float v0, v1;
                    if (k < 192) {
                        const float* Hs = (k < 64) ? hl_s : ((k < 128) ? ht_s : hd_s);
                        int ko = k & 63;
                        v0 = Ys[m0 * YSTR + k] * Hs[m0 * 64 + ko];
                        v1 = Ys[m1 * YSTR + k] * Hs[m1 * 64 + ko];
                    } else {
                        v0 = Xc[m0 * 16 + (k - 192)]; v1 = Xc[m1 * 16 + (k - 192)];
                    }
                    As[k * 8 + mp_b] = make_float2(v0, v1);
                }
            }
        }
        __syncthreads();

        // ---- stage-2 GEMM: acc2[mp] ----
        unsigned long long acc2[8];
#pragma unroll
        for (int m = 0; m < 8; m++) acc2[m] = 0ULL;
        {
#pragma unroll 4
            for (int kk = 0; kk < 52; kk++) {
                ulonglong2 a[4];
                LDA(a, kk);
                unsigned long long wd = dup2(w4[kk & 3]);
                if (kk + 4 < 52) w4[kk & 3] = wp2[(kk + 4) * 64];
                FMA2(acc2[0], a[0].x, wd); FMA2(acc2[1], a[0].y, wd);
                FMA2(acc2[2], a[1].x, wd); FMA2(acc2[3], a[1].y, wd);
                FMA2(acc2[4], a[2].x, wd); FMA2(acc2[5], a[2].y, wd);
                FMA2(acc2[6], a[3].x, wd); FMA2(acc2[7], a[3].y, wd);
            }
        }
#pragma unroll
        for (int m = 0; m < 8; m++)
            Pv[(size_t)kg * 512 + m * 64 + nl] = unpack2(acc2[m]);
        __syncthreads();

        // ---- reduce + tanh + differenced-softmax gates + H update ----
        {
            float* Gout = g_H + ((size_t)(l * 64 + r)) * 4096 + b0 * 64;
            const bool last = (l == 63) && (r == 63);
#pragma unroll
            for (int i = 0; i < 2; i++) {
                int f = tid + 256 * i;
                int nl2 = f & 63, m = f >> 6;
                int base = m * 64 + nl2;
                float2 s0 = Pv[base], s1 = Pv[512 + base];
                float2 s2 = Pv[1024 + base], s3 = Pv[1536 + base];
                float wb = wijb[nl2];
                float av[2] = {((s0.x + s1.x) + (s2.x + s3.x)) + wb,
                               ((s0.y + s1.y) + (s2.y + s3.y)) + wb};
#pragma unroll
                for (int h2 = 0; h2 < 2; h2++) {
                    int mm = 2 * m + h2;
                    int u = nl2;
                    float hnew = fast_tanh(av[h2]);
                    const float* zrow = Ys + mm * YSTR + 192;
                    float z1 = zrow[u], z2 = zrow[64 + u], z3 = zrow[128 + u];
                    float mx = fmaxf(fmaxf(z1, z2), fmaxf(z3, 0.0f));
                    float e0 = __expf(-mx);
                    float e1 = __expf(z1 - mx), e2 = __expf(z2 - mx), e3 = __expf(z3 - mx);
                    float inv = __fdividef(1.0f, e0 + e1 + e2 + e3);
                    float h = (e0 * hnew + e1 * hl_s[mm * 64 + u] +
                               e2 * ht_s[mm * 64 + u] + e3 * hd_s[mm * 64 + u]) * inv;
                    hdst[mm * 64 + u] = h;
                    if (sub == 1) Gout[mm * 64 + u] = h;
                    if (last) out[(b0 + mm) * 64 + u] = h;
                }
            }
        }
        __syncthreads();

        if (sub == 1 && tid == 0) {
            __threadfence();
            int* fp = &g_flag[(q * 64 + l) * 64 + r];
            asm volatile("st.release.gpu.global.b32 [%0], %1;" :: "l"(fp), "r"(1) : "memory");
        }
    }
}

extern "C" void kernel_launch(void* const* d_in, const int* in_sizes, int n_in,
                              void* d_out, int out_size)
{
    const float* inputs = (const float*)d_in[0];
    const float* wr_w   = (const float*)d_in[1];
    const float* wr_b   = (const float*)d_in[2];
    const float* wz_w   = (const float*)d_in[3];
    const float* wz_b   = (const float*)d_in[4];
    const float* wij_w  = (const float*)d_in[5];
    const float* wij_b  = (const float*)d_in[6];
    const float* U_w    = (const float*)d_in[7];
    float* out = (float*)d_out;

    cudaFuncSetAttribute(pipeline_kernel, cudaFuncAttributeMaxDynamicSharedMemorySize, SMEM_BYTES);

    init_kernel<<<512, 256>>>(inputs, wr_w, wz_w, U_w, wij_w);
    pipeline_kernel<<<128, 256, SMEM_BYTES>>>(wr_b, wz_b, wij_b, out);
}